// round 8
// baseline (speedup 1.0000x reference)
#include <cuda_runtime.h>
#include <cstdint>

#define B_  4
#define T_  1024
#define TT  2048
#define D_  512
#define H_  8
#define HD  64

// Scratch (allocation-free rule: __device__ globals).
__device__ float g_Q[B_*H_*TT*HD];     // tf32-rounded (b,h,t,hd), natural
__device__ float g_K[B_*H_*TT*HD];     // tf32-rounded (b,h,t,hd), hd interleaved in 8-blocks
__device__ float g_Vt[B_*H_*HD*TT];    // tf32-rounded V^T (b,h,hd,t), t interleaved in 8-blocks
__device__ float g_Y[B_*TT*D_];        // attention out, tf32-rounded (b,t,d)
// tf32-rounded copies of inputs (pre-pass)
__device__ float g_rXs[B_*T_*D_];
__device__ float g_rXc[B_*T_*D_];
__device__ float g_rWs[D_*3*D_];
__device__ float g_rWc[D_*3*D_];
__device__ float g_rWp[D_*D_];

__device__ __forceinline__ uint32_t f2tf32(float x) {
    uint32_t r;
    asm("cvt.rna.tf32.f32 %0, %1;" : "=r"(r) : "f"(x));
    return r;
}
__device__ __forceinline__ float fexp2(float x) {
    float y;
    asm("ex2.approx.f32 %0, %1;" : "=f"(y) : "f"(x));
    return y;
}
// interleave within 8-blocks: k=th and k=th+4 become adjacent
__device__ __forceinline__ int ilv8(int k) {
    return (k & ~7) | ((k & 3) << 1) | ((k & 4) >> 2);
}
__device__ __forceinline__ void mma16n8k8(float* c, const uint32_t* a,
                                          uint32_t b0, uint32_t b1) {
    asm volatile(
        "mma.sync.aligned.m16n8k8.row.col.f32.tf32.tf32.f32 "
        "{%0,%1,%2,%3}, {%4,%5,%6,%7}, {%8,%9}, {%0,%1,%2,%3};"
        : "+f"(c[0]), "+f"(c[1]), "+f"(c[2]), "+f"(c[3])
        : "r"(a[0]), "r"(a[1]), "r"(a[2]), "r"(a[3]), "r"(b0), "r"(b1));
}
__device__ __forceinline__ void cp16(uint32_t dst, const void* src) {
    asm volatile("cp.async.cg.shared.global [%0], [%1], 16;"
                 :: "r"(dst), "l"(src) : "memory");
}
#define CP_COMMIT() asm volatile("cp.async.commit_group;" ::: "memory")
#define CP_WAIT(n)  asm volatile("cp.async.wait_group %0;" :: "n"(n) : "memory")
__device__ __forceinline__ uint32_t smem_u32(const void* p) {
    uint32_t a;
    asm("{ .reg .u64 t; cvta.to.shared.u64 t, %1; cvt.u32.u64 %0, t; }"
        : "=r"(a) : "l"(p));
    return a;
}

// ============================================================================
// Pre-pass (single launch): RNA-round all five inputs to tf32 copies
// ============================================================================
#define N4_X  (B_*T_*D_/4)       // 524288
#define N4_W3 (D_*3*D_/4)        // 196608
#define N4_WP (D_*D_/4)          // 65536
#define N4_TOT (2*N4_X + 2*N4_W3 + N4_WP)

__global__ __launch_bounds__(256) void round_all(
    const float* __restrict__ Xs, const float* __restrict__ Xc,
    const float* __restrict__ Ws, const float* __restrict__ Wc,
    const float* __restrict__ Wp)
{
    int i = blockIdx.x * 256 + threadIdx.x;
    if (i >= N4_TOT) return;
    const float4* src; float4* dst; int j;
    if (i < N4_X)                    { src = (const float4*)Xs; dst = (float4*)g_rXs; j = i; }
    else if (i < 2*N4_X)             { src = (const float4*)Xc; dst = (float4*)g_rXc; j = i - N4_X; }
    else if (i < 2*N4_X + N4_W3)     { src = (const float4*)Ws; dst = (float4*)g_rWs; j = i - 2*N4_X; }
    else if (i < 2*N4_X + 2*N4_W3)   { src = (const float4*)Wc; dst = (float4*)g_rWc; j = i - 2*N4_X - N4_W3; }
    else                             { src = (const float4*)Wp; dst = (float4*)g_rWp; j = i - 2*N4_X - 2*N4_W3; }
    float4 v = src[j];
    uint4 t = make_uint4(f2tf32(v.x), f2tf32(v.y), f2tf32(v.z), f2tf32(v.w));
    ((uint4*)dst)[j] = t;
}

// ============================================================================
// QKV GEMM, tf32 mma.sync, cp.async double-buffered.
// K epilogue: hd interleaved. V epilogue: V^T with t interleaved.
// ============================================================================
#define LDA 36
#define LDB 136
#define ABYTES (128*LDA*4)
#define SLABF  (128*LDA + 32*LDB)
#define GEMM_SMEM (2*SLABF*4)

__global__ __launch_bounds__(256, 2) void qkv_mma(
    const float* __restrict__ bS, const float* __restrict__ bC)
{
    extern __shared__ float smf[];
    const uint32_t sbU = smem_u32(smf);

    const int z = blockIdx.z;
    const float* X    = z ? g_rXc : g_rXs;
    const float* W    = z ? g_rWc : g_rWs;
    const float* bias = z ? bC : bS;
    const int seq_off = z ? 1024 : 0;

    const int tid  = threadIdx.x;
    const int wid  = tid >> 5, lane = tid & 31;
    const int g = lane >> 2, th = lane & 3;
    const int wm = wid & 3, wn = wid >> 2;
    const int m0 = blockIdx.y * 128, n0 = blockIdx.x * 128;

    auto stage = [&](int k0, int buf) {
        const uint32_t adst = sbU + (buf ? (uint32_t)(SLABF*4) : 0u);
        const uint32_t bdst = adst + ABYTES;
        #pragma unroll
        for (int i = 0; i < 4; i++) {
            int cid = tid + i * 256;
            int r = cid >> 3, kc = cid & 7;
            cp16(adst + (r*LDA + kc*4)*4, X + (size_t)(m0 + r)*512 + k0 + kc*4);
        }
        #pragma unroll
        for (int i = 0; i < 4; i++) {
            int cid = tid + i * 256;
            int kr = cid >> 5, nc = cid & 31;
            cp16(bdst + (kr*LDB + nc*4)*4, W + (size_t)(k0 + kr)*1536 + n0 + nc*4);
        }
        CP_COMMIT();
    };

    float acc[2][8][4];
    #pragma unroll
    for (int mt = 0; mt < 2; mt++)
        #pragma unroll
        for (int nt = 0; nt < 8; nt++)
            #pragma unroll
            for (int j = 0; j < 4; j++) acc[mt][nt][j] = 0.f;

    stage(0, 0);
    #pragma unroll 1
    for (int it = 0; it < 16; it++) {
        const int buf = it & 1;
        if (it < 15) { stage((it + 1) * 32, buf ^ 1); CP_WAIT(1); }
        else         { CP_WAIT(0); }
        __syncthreads();

        const float* As = smf + (buf ? SLABF : 0);
        const float* Bs = As + 128*LDA;

        #pragma unroll
        for (int s = 0; s < 4; s++) {
            uint32_t aF[2][4];
            #pragma unroll
            for (int mt = 0; mt < 2; mt++) {
                int rb = wm * 32 + mt * 16 + g;
                aF[mt][0] = __float_as_uint(As[rb * LDA + s*8 + th]);
                aF[mt][1] = __float_as_uint(As[(rb + 8) * LDA + s*8 + th]);
                aF[mt][2] = __float_as_uint(As[rb * LDA + s*8 + th + 4]);
                aF[mt][3] = __float_as_uint(As[(rb + 8) * LDA + s*8 + th + 4]);
            }
            #pragma unroll
            for (int nt = 0; nt < 8; nt++) {
                int nc = wn * 64 + nt * 8 + g;
                uint32_t b0 = __float_as_uint(Bs[(s*8 + th) * LDB + nc]);
                uint32_t b1 = __float_as_uint(Bs[(s*8 + th + 4) * LDB + nc]);
                mma16n8k8(acc[0][nt], aF[0], b0, b1);
                mma16n8k8(acc[1][nt], aF[1], b0, b1);
            }
        }
        __syncthreads();
    }

    #pragma unroll
    for (int mt = 0; mt < 2; mt++) {
        #pragma unroll
        for (int r2 = 0; r2 < 2; r2++) {
            int row = m0 + wm * 32 + mt * 16 + g + r2 * 8;
            int bb = row >> 10;
            int tg = (row & 1023) + seq_off;
            #pragma unroll
            for (int nt = 0; nt < 8; nt++) {
                int col = n0 + wn * 64 + nt * 8 + 2 * th;
                float v0 = acc[mt][nt][r2*2+0] + bias[col];
                float v1 = acc[mt][nt][r2*2+1] + bias[col+1];
                int sel = col >> 9, c = col & 511;
                int h = c >> 6, dd = c & 63;
                if (sel == 2) {
                    // V^T with interleaved t
                    int tgp = (tg & ~7) | ((tg & 3) << 1) | ((tg & 4) >> 2);
                    float* dv = g_Vt + ((((size_t)bb * H_ + h) * HD + dd) * TT) + tgp;
                    dv[0]  = __uint_as_float(f2tf32(v0));
                    dv[TT] = __uint_as_float(f2tf32(v1));
                } else if (sel == 1) {
                    // K with interleaved hd
                    size_t base = (((size_t)bb * H_ + h) * TT + tg) << 6;
                    g_K[base + ilv8(dd)]     = __uint_as_float(f2tf32(v0));
                    g_K[base + ilv8(dd + 1)] = __uint_as_float(f2tf32(v1));
                } else {
                    size_t off = ((((size_t)bb * H_ + h) * TT + tg) << 6) + dd;
                    g_Q[off]     = __uint_as_float(f2tf32(v0));
                    g_Q[off + 1] = __uint_as_float(f2tf32(v1));
                }
            }
        }
    }
}

// ============================================================================
// Flash attention, all-tf32. 8 warps x 16 q-rows (CTA = 128 q-rows),
// 2 CTAs/SM. K-tiles of 64, cp.async double-buffered.
// B-fragments (K, V) load as single LDS.64 via interleaved k-dim layouts.
// ============================================================================
#define KT  64
#define NKT 32
#define LDK 68
#define LDV 68
#define LDP 68
#define K0B 0
#define K1B 17408
#define V0B 34816
#define V1B 52224
#define PB  69632
#define T0B 104448
#define T1B 104704
#define ATTN_SMEM 104960

__global__ __launch_bounds__(256, 2) void attn_mma(
    const int* __restrict__ t_self, const int* __restrict__ t_cross)
{
    extern __shared__ char smc[];
    const uint32_t sbU = smem_u32(smc);

    const int tid  = threadIdx.x;
    const int wid  = tid >> 5;
    const int lane = tid & 31;
    const int g    = lane >> 2;
    const int th   = lane & 3;
    const int bh   = blockIdx.y, b = bh >> 3, h = bh & 7;
    const int q0   = blockIdx.x * 128;

    const float* Qg = g_Q + (size_t)bh * TT * HD;
    const float* Kg = g_K + (size_t)bh * TT * HD;
    const float* Vg = g_Vt + (size_t)bh * HD * TT;

    auto issue = [&](int kt, int bufsel) {
        const int k0 = kt * KT;
        const uint32_t kdst = sbU + (bufsel ? K1B : K0B);
        const uint32_t vdst = sbU + (bufsel ? V1B : V0B);
        #pragma unroll
        for (int i = 0; i < 4; i++) {           // K: 64 t-rows x 256B
            int idx = tid + i * 256;
            int row = idx >> 4, c = idx & 15;
            cp16(kdst + row * (LDK*4) + c * 16,
                 Kg + (size_t)(k0 + row) * HD + c * 4);
        }
        #pragma unroll
        for (int i = 0; i < 4; i++) {           // V^T: 64 hd-rows x 256B
            int idx = tid + i * 256;
            int row = idx >> 4, c = idx & 15;
            cp16(vdst + row * (LDV*4) + c * 16,
                 Vg + (size_t)row * TT + k0 + c * 4);
        }
        if (tid < 16) {
            const int* tb = (k0 < T_) ? (t_self + b * T_ + k0)
                                      : (t_cross + b * T_ + k0 - T_);
            cp16(sbU + (bufsel ? T1B : T0B) + tid * 16, tb + tid * 4);
        }
        CP_COMMIT();
    };
    issue(0, 0);

    const int wr = q0 + wid * 16;

    // Q fragments resident (natural hd indices; K side carries the interleave)
    uint32_t aQ[8][4];
    {
        const float* qp0 = Qg + (size_t)(wr + g) * HD;
        const float* qp1 = Qg + (size_t)(wr + g + 8) * HD;
        #pragma unroll
        for (int s = 0; s < 8; s++) {
            aQ[s][0] = __float_as_uint(qp0[s*8 + th]);
            aQ[s][1] = __float_as_uint(qp1[s*8 + th]);
            aQ[s][2] = __float_as_uint(qp0[s*8 + th + 4]);
            aQ[s][3] = __float_as_uint(qp1[s*8 + th + 4]);
        }
    }
    int tq[2];
    #pragma unroll
    for (int rr = 0; rr < 2; rr++) {
        int qg = wr + g + rr*8;
        tq[rr] = (qg < T_) ? t_self[b*T_ + qg] : t_cross[b*T_ + qg - T_];
    }

    float oacc[8][4];
    #pragma unroll
    for (int n = 0; n < 8; n++)
        #pragma unroll
        for (int j = 0; j < 4; j++) oacc[n][j] = 0.f;
    float l0 = 0.f, l1 = 0.f;

    float* Pw = (float*)(smc + PB) + wid * 16 * LDP;
    const float E = 0.125f * 1.44269504f;

    #pragma unroll 1
    for (int kt = 0; kt < NKT; kt++) {
        const int buf = kt & 1;
        if (kt < NKT - 1) { issue(kt + 1, buf ^ 1); CP_WAIT(1); }
        else              { CP_WAIT(0); }
        __syncthreads();

        const float* Ks  = (const float*)(smc + (buf ? K1B : K0B));
        const float* Vs  = (const float*)(smc + (buf ? V1B : V0B));
        const int*   tks = (const int*)(smc + (buf ? T1B : T0B));

        // ---- S = Q K^T, mask/exp, store P (tf32) ----
        #pragma unroll
        for (int nb = 0; nb < 8; nb++) {
            float sa[4] = {0.f, 0.f, 0.f, 0.f};
            const float* krow = &Ks[(nb*8 + g) * LDK];
            #pragma unroll
            for (int s = 0; s < 8; s++) {
                uint2 kb = *(const uint2*)&krow[s*8 + 2*th];   // LDS.64
                mma16n8k8(sa, aQ[s], kb.x, kb.y);
            }
            const int c0 = nb*8 + 2*th;
            const int tk0 = tks[c0], tk1 = tks[c0 + 1];

            float p00 = (tq[0] >= tk0) ? fexp2(sa[0] * E) : 0.f;
            float p01 = (tq[0] >= tk1) ? fexp2(sa[1] * E) : 0.f;
            float p10 = (tq[1] >= tk0) ? fexp2(sa[2] * E) : 0.f;
            float p11 = (tq[1] >= tk1) ? fexp2(sa[3] * E) : 0.f;
            l0 += p00 + p01;  l1 += p10 + p11;
            *(uint2*)&Pw[g * LDP + c0]       = make_uint2(f2tf32(p00), f2tf32(p01));
            *(uint2*)&Pw[(g + 8) * LDP + c0] = make_uint2(f2tf32(p10), f2tf32(p11));
        }
        __syncwarp();   // P is per-warp private

        // ---- O += P V (tf32 m16n8k8; V^T rows = hd, t interleaved) ----
        #pragma unroll
        for (int s2 = 0; s2 < 8; s2++) {
            uint32_t aP[4];
            aP[0] = __float_as_uint(Pw[g * LDP + s2*8 + th]);
            aP[1] = __float_as_uint(Pw[(g + 8) * LDP + s2*8 + th]);
            aP[2] = __float_as_uint(Pw[g * LDP + s2*8 + th + 4]);
            aP[3] = __float_as_uint(Pw[(g + 8) * LDP + s2*8 + th + 4]);
            #pragma unroll
            for (int nb2 = 0; nb2 < 8; nb2++) {
                const float* vrow = &Vs[(nb2*8 + g) * LDV];
                uint2 vb = *(const uint2*)&vrow[s2*8 + 2*th];  // LDS.64
                mma16n8k8(oacc[nb2], aP, vb.x, vb.y);
            }
        }
        __syncthreads();   // all reads of buf done before refill
    }

    l0 += __shfl_xor_sync(0xffffffffu, l0, 1);
    l0 += __shfl_xor_sync(0xffffffffu, l0, 2);
    l1 += __shfl_xor_sync(0xffffffffu, l1, 1);
    l1 += __shfl_xor_sync(0xffffffffu, l1, 2);
    float inv[2] = {1.f / l0, 1.f / l1};

    #pragma unroll
    for (int rr = 0; rr < 2; rr++) {
        int row = wr + g + rr*8;
        float* d = g_Y + ((size_t)(b * TT + row)) * D_ + h * HD;
        #pragma unroll
        for (int nb2 = 0; nb2 < 8; nb2++) {
            int c = nb2*8 + 2*th;
            *(uint2*)&d[c] = make_uint2(f2tf32(oacc[nb2][rr*2+0] * inv[rr]),
                                        f2tf32(oacc[nb2][rr*2+1] * inv[rr]));
        }
    }
}

// ============================================================================
// Proj GEMM, tf32 mma.sync, cp.async double-buffered (unchanged)
// ============================================================================
__global__ __launch_bounds__(256, 2) void proj_mma(
    const float* __restrict__ bias, float* __restrict__ out)
{
    extern __shared__ float smf[];
    const uint32_t sbU = smem_u32(smf);

    const int tid  = threadIdx.x;
    const int wid  = tid >> 5, lane = tid & 31;
    const int g = lane >> 2, th = lane & 3;
    const int wm = wid & 3, wn = wid >> 2;
    const int m0 = blockIdx.y * 128, n0 = blockIdx.x * 128;

    auto stage = [&](int k0, int buf) {
        const uint32_t adst = sbU + (buf ? (uint32_t)(SLABF*4) : 0u);
        const uint32_t bdst = adst + ABYTES;
        #pragma unroll
        for (int i = 0; i < 4; i++) {
            int cid = tid + i * 256;
            int r = cid >> 3, kc = cid & 7;
            cp16(adst + (r*LDA + kc*4)*4, g_Y + (size_t)(m0 + r)*512 + k0 + kc*4);
        }
        #pragma unroll
        for (int i = 0; i < 4; i++) {
            int cid = tid + i * 256;
            int kr = cid >> 5, nc = cid & 31;
            cp16(bdst + (kr*LDB + nc*4)*4, g_rWp + (size_t)(k0 + kr)*512 + n0 + nc*4);
        }
        CP_COMMIT();
    };

    float acc[2][8][4];
    #pragma unroll
    for (int mt = 0; mt < 2; mt++)
        #pragma unroll
        for (int nt = 0; nt < 8; nt++)
            #pragma unroll
            for (int j = 0; j < 4; j++) acc[mt][nt][j] = 0.f;

    stage(0, 0);
    #pragma unroll 1
    for (int it = 0; it < 16; it++) {
        const int buf = it & 1;
        if (it < 15) { stage((it + 1) * 32, buf ^ 1); CP_WAIT(1); }
        else         { CP_WAIT(0); }
        __syncthreads();

        const float* As = smf + (buf ? SLABF : 0);
        const float* Bs = As + 128*LDA;

        #pragma unroll
        for (int s = 0; s < 4; s++) {
            uint32_t aF[2][4];
            #pragma unroll
            for (int mt = 0; mt < 2; mt++) {
                int rb = wm * 32 + mt * 16 + g;
                aF[mt][0] = __float_as_uint(As[rb * LDA + s*8 + th]);
                aF[mt][1] = __float_as_uint(As[(rb + 8) * LDA + s*8 + th]);
                aF[mt][2] = __float_as_uint(As[rb * LDA + s*8 + th + 4]);
                aF[mt][3] = __float_as_uint(As[(rb + 8) * LDA + s*8 + th + 4]);
            }
            #pragma unroll
            for (int nt = 0; nt < 8; nt++) {
                int nc = wn * 64 + nt * 8 + g;
                uint32_t b0 = __float_as_uint(Bs[(s*8 + th) * LDB + nc]);
                uint32_t b1 = __float_as_uint(Bs[(s*8 + th + 4) * LDB + nc]);
                mma16n8k8(acc[0][nt], aF[0], b0, b1);
                mma16n8k8(acc[1][nt], aF[1], b0, b1);
            }
        }
        __syncthreads();
    }

    #pragma unroll
    for (int mt = 0; mt < 2; mt++) {
        #pragma unroll
        for (int r2 = 0; r2 < 2; r2++) {
            int row = m0 + wm * 32 + mt * 16 + g + r2 * 8;
            int bb = row >> 11;
            int tt = row & 2047;
            size_t base = (tt < T_)
                ? ((size_t)(bb * T_ + tt) * D_)
                : ((size_t)B_ * T_ * D_ + (size_t)(bb * T_ + (tt - T_)) * D_);
            #pragma unroll
            for (int nt = 0; nt < 8; nt++) {
                int col = n0 + wn * 64 + nt * 8 + 2 * th;
                float2 v = make_float2(acc[mt][nt][r2*2+0] + bias[col],
                                       acc[mt][nt][r2*2+1] + bias[col+1]);
                *(float2*)&out[base + col] = v;
            }
        }
    }
}

// ---------------------------------------------------------------------------
extern "C" void kernel_launch(void* const* d_in, const int* in_sizes, int n_in,
                              void* d_out, int out_size)
{
    const float* self_seq  = (const float*)d_in[0];
    const float* cross_seq = (const float*)d_in[1];
    const int*   t_self    = (const int*)d_in[2];
    const int*   t_cross   = (const int*)d_in[3];
    const float* W_self    = (const float*)d_in[4];
    const float* b_self    = (const float*)d_in[5];
    const float* W_cross   = (const float*)d_in[6];
    const float* b_cross   = (const float*)d_in[7];
    const float* W_proj    = (const float*)d_in[8];
    const float* b_proj    = (const float*)d_in[9];
    float* out = (float*)d_out;

    cudaFuncSetAttribute(attn_mma,
                         cudaFuncAttributeMaxDynamicSharedMemorySize, ATTN_SMEM);
    cudaFuncSetAttribute(qkv_mma,
                         cudaFuncAttributeMaxDynamicSharedMemorySize, GEMM_SMEM);
    cudaFuncSetAttribute(proj_mma,
                         cudaFuncAttributeMaxDynamicSharedMemorySize, GEMM_SMEM);

    round_all<<<(N4_TOT + 255)/256, 256>>>(self_seq, cross_seq,
                                           W_self, W_cross, W_proj);

    qkv_mma<<<dim3(12, 32, 2), 256, GEMM_SMEM>>>(b_self, b_cross);

    attn_mma<<<dim3(16, 32), 256, ATTN_SMEM>>>(t_self, t_cross);

    proj_mma<<<dim3(4, 64), 256, GEMM_SMEM>>>(b_proj, out);
}

// round 9
// speedup vs baseline: 1.2558x; 1.2558x over previous
#include <cuda_runtime.h>
#include <cstdint>

#define B_  4
#define T_  1024
#define TT  2048
#define D_  512
#define H_  8
#define HD  64

// Scratch (allocation-free rule: __device__ globals).
__device__ float g_Q[B_*H_*TT*HD];     // tf32-rounded (b,h,t,hd), natural
__device__ float g_K[B_*H_*TT*HD];     // tf32-rounded (b,h,t,hd), hd interleaved in 8-blocks
__device__ float g_Vt[B_*H_*HD*TT];    // tf32-rounded V^T (b,h,hd,t), t interleaved in 8-blocks
__device__ float g_Y[B_*TT*D_];        // attention out, tf32-rounded (b,t,d)
// tf32-rounded copies of inputs (pre-pass)
__device__ float g_rXs[B_*T_*D_];
__device__ float g_rXc[B_*T_*D_];
__device__ float g_rWs[D_*3*D_];
__device__ float g_rWc[D_*3*D_];
__device__ float g_rWp[D_*D_];

__device__ __forceinline__ uint32_t f2tf32(float x) {
    uint32_t r;
    asm("cvt.rna.tf32.f32 %0, %1;" : "=r"(r) : "f"(x));
    return r;
}
__device__ __forceinline__ float fexp2(float x) {
    float y;
    asm("ex2.approx.f32 %0, %1;" : "=f"(y) : "f"(x));
    return y;
}
// interleave within 8-blocks: k=th and k=th+4 become adjacent
__device__ __forceinline__ int ilv8(int k) {
    return (k & ~7) | ((k & 3) << 1) | ((k & 4) >> 2);
}
__device__ __forceinline__ void mma16n8k8(float* c, const uint32_t* a,
                                          uint32_t b0, uint32_t b1) {
    asm volatile(
        "mma.sync.aligned.m16n8k8.row.col.f32.tf32.tf32.f32 "
        "{%0,%1,%2,%3}, {%4,%5,%6,%7}, {%8,%9}, {%0,%1,%2,%3};"
        : "+f"(c[0]), "+f"(c[1]), "+f"(c[2]), "+f"(c[3])
        : "r"(a[0]), "r"(a[1]), "r"(a[2]), "r"(a[3]), "r"(b0), "r"(b1));
}
__device__ __forceinline__ void cp16(uint32_t dst, const void* src) {
    asm volatile("cp.async.cg.shared.global [%0], [%1], 16;"
                 :: "r"(dst), "l"(src) : "memory");
}
#define CP_COMMIT() asm volatile("cp.async.commit_group;" ::: "memory")
#define CP_WAIT(n)  asm volatile("cp.async.wait_group %0;" :: "n"(n) : "memory")
__device__ __forceinline__ uint32_t smem_u32(const void* p) {
    uint32_t a;
    asm("{ .reg .u64 t; cvta.to.shared.u64 t, %1; cvt.u32.u64 %0, t; }"
        : "=r"(a) : "l"(p));
    return a;
}

// ============================================================================
// Pre-pass (single launch): RNA-round all five inputs to tf32 copies
// ============================================================================
#define N4_X  (B_*T_*D_/4)
#define N4_W3 (D_*3*D_/4)
#define N4_WP (D_*D_/4)
#define N4_TOT (2*N4_X + 2*N4_W3 + N4_WP)

__global__ __launch_bounds__(256) void round_all(
    const float* __restrict__ Xs, const float* __restrict__ Xc,
    const float* __restrict__ Ws, const float* __restrict__ Wc,
    const float* __restrict__ Wp)
{
    int i = blockIdx.x * 256 + threadIdx.x;
    if (i >= N4_TOT) return;
    const float4* src; float4* dst; int j;
    if (i < N4_X)                    { src = (const float4*)Xs; dst = (float4*)g_rXs; j = i; }
    else if (i < 2*N4_X)             { src = (const float4*)Xc; dst = (float4*)g_rXc; j = i - N4_X; }
    else if (i < 2*N4_X + N4_W3)     { src = (const float4*)Ws; dst = (float4*)g_rWs; j = i - 2*N4_X; }
    else if (i < 2*N4_X + 2*N4_W3)   { src = (const float4*)Wc; dst = (float4*)g_rWc; j = i - 2*N4_X - N4_W3; }
    else                             { src = (const float4*)Wp; dst = (float4*)g_rWp; j = i - 2*N4_X - 2*N4_W3; }
    float4 v = src[j];
    uint4 t = make_uint4(f2tf32(v.x), f2tf32(v.y), f2tf32(v.z), f2tf32(v.w));
    ((uint4*)dst)[j] = t;
}

// ============================================================================
// QKV GEMM, tf32 mma.sync, cp.async double-buffered.
// K epilogue: hd interleaved. V epilogue: V^T with t interleaved.
// ============================================================================
#define LDA 36
#define LDB 136
#define ABYTES (128*LDA*4)
#define SLABF  (128*LDA + 32*LDB)
#define GEMM_SMEM (2*SLABF*4)

__global__ __launch_bounds__(256, 2) void qkv_mma(
    const float* __restrict__ bS, const float* __restrict__ bC)
{
    extern __shared__ float smf[];
    const uint32_t sbU = smem_u32(smf);

    const int z = blockIdx.z;
    const float* X    = z ? g_rXc : g_rXs;
    const float* W    = z ? g_rWc : g_rWs;
    const float* bias = z ? bC : bS;
    const int seq_off = z ? 1024 : 0;

    const int tid  = threadIdx.x;
    const int wid  = tid >> 5, lane = tid & 31;
    const int g = lane >> 2, th = lane & 3;
    const int wm = wid & 3, wn = wid >> 2;
    const int m0 = blockIdx.y * 128, n0 = blockIdx.x * 128;

    auto stage = [&](int k0, int buf) {
        const uint32_t adst = sbU + (buf ? (uint32_t)(SLABF*4) : 0u);
        const uint32_t bdst = adst + ABYTES;
        #pragma unroll
        for (int i = 0; i < 4; i++) {
            int cid = tid + i * 256;
            int r = cid >> 3, kc = cid & 7;
            cp16(adst + (r*LDA + kc*4)*4, X + (size_t)(m0 + r)*512 + k0 + kc*4);
        }
        #pragma unroll
        for (int i = 0; i < 4; i++) {
            int cid = tid + i * 256;
            int kr = cid >> 5, nc = cid & 31;
            cp16(bdst + (kr*LDB + nc*4)*4, W + (size_t)(k0 + kr)*1536 + n0 + nc*4);
        }
        CP_COMMIT();
    };

    float acc[2][8][4];
    #pragma unroll
    for (int mt = 0; mt < 2; mt++)
        #pragma unroll
        for (int nt = 0; nt < 8; nt++)
            #pragma unroll
            for (int j = 0; j < 4; j++) acc[mt][nt][j] = 0.f;

    stage(0, 0);
    #pragma unroll 1
    for (int it = 0; it < 16; it++) {
        const int buf = it & 1;
        if (it < 15) { stage((it + 1) * 32, buf ^ 1); CP_WAIT(1); }
        else         { CP_WAIT(0); }
        __syncthreads();

        const float* As = smf + (buf ? SLABF : 0);
        const float* Bs = As + 128*LDA;

        #pragma unroll
        for (int s = 0; s < 4; s++) {
            uint32_t aF[2][4];
            #pragma unroll
            for (int mt = 0; mt < 2; mt++) {
                int rb = wm * 32 + mt * 16 + g;
                aF[mt][0] = __float_as_uint(As[rb * LDA + s*8 + th]);
                aF[mt][1] = __float_as_uint(As[(rb + 8) * LDA + s*8 + th]);
                aF[mt][2] = __float_as_uint(As[rb * LDA + s*8 + th + 4]);
                aF[mt][3] = __float_as_uint(As[(rb + 8) * LDA + s*8 + th + 4]);
            }
            #pragma unroll
            for (int nt = 0; nt < 8; nt++) {
                int nc = wn * 64 + nt * 8 + g;
                uint32_t b0 = __float_as_uint(Bs[(s*8 + th) * LDB + nc]);
                uint32_t b1 = __float_as_uint(Bs[(s*8 + th + 4) * LDB + nc]);
                mma16n8k8(acc[0][nt], aF[0], b0, b1);
                mma16n8k8(acc[1][nt], aF[1], b0, b1);
            }
        }
        __syncthreads();
    }

    #pragma unroll
    for (int mt = 0; mt < 2; mt++) {
        #pragma unroll
        for (int r2 = 0; r2 < 2; r2++) {
            int row = m0 + wm * 32 + mt * 16 + g + r2 * 8;
            int bb = row >> 10;
            int tg = (row & 1023) + seq_off;
            #pragma unroll
            for (int nt = 0; nt < 8; nt++) {
                int col = n0 + wn * 64 + nt * 8 + 2 * th;
                float v0 = acc[mt][nt][r2*2+0] + bias[col];
                float v1 = acc[mt][nt][r2*2+1] + bias[col+1];
                int sel = col >> 9, c = col & 511;
                int h = c >> 6, dd = c & 63;
                if (sel == 2) {
                    // V^T with interleaved t
                    int tgp = (tg & ~7) | ((tg & 3) << 1) | ((tg & 4) >> 2);
                    float* dv = g_Vt + ((((size_t)bb * H_ + h) * HD + dd) * TT) + tgp;
                    dv[0]  = __uint_as_float(f2tf32(v0));
                    dv[TT] = __uint_as_float(f2tf32(v1));
                } else if (sel == 1) {
                    // K with interleaved hd
                    size_t base = (((size_t)bb * H_ + h) * TT + tg) << 6;
                    g_K[base + ilv8(dd)]     = __uint_as_float(f2tf32(v0));
                    g_K[base + ilv8(dd + 1)] = __uint_as_float(f2tf32(v1));
                } else {
                    size_t off = ((((size_t)bb * H_ + h) * TT + tg) << 6) + dd;
                    g_Q[off]     = __uint_as_float(f2tf32(v0));
                    g_Q[off + 1] = __uint_as_float(f2tf32(v1));
                }
            }
        }
    }
}

// ============================================================================
// Flash attention, all-tf32. 8 warps x 16 q-rows (CTA = 128 q-rows),
// 2 CTAs/SM. K-tiles of 64, cp.async double-buffered.
// B-fragments (K, V) are single conflict-free LDS.64:
//   layouts interleave k within 8-blocks; LDK=LDV=72 makes the 8-byte word
//   index = 36g+th = 4g+th (mod 16) -> distinct per 16-lane phase.
// ============================================================================
#define KT  64
#define NKT 32
#define LDK 72
#define LDV 72
#define LDP 68
#define K0B 0
#define K1B 18432
#define V0B 36864
#define V1B 55296
#define PB  73728                 // 8 warps x 16 x LDP x 4 = 34816
#define T0B 108544
#define T1B 108800
#define ATTN_SMEM 109056

__global__ __launch_bounds__(256, 2) void attn_mma(
    const int* __restrict__ t_self, const int* __restrict__ t_cross)
{
    extern __shared__ char smc[];
    const uint32_t sbU = smem_u32(smc);

    const int tid  = threadIdx.x;
    const int wid  = tid >> 5;
    const int lane = tid & 31;
    const int g    = lane >> 2;
    const int th   = lane & 3;
    const int bh   = blockIdx.y, b = bh >> 3, h = bh & 7;
    const int q0   = blockIdx.x * 128;

    const float* Qg = g_Q + (size_t)bh * TT * HD;
    const float* Kg = g_K + (size_t)bh * TT * HD;
    const float* Vg = g_Vt + (size_t)bh * HD * TT;

    auto issue = [&](int kt, int bufsel) {
        const int k0 = kt * KT;
        const uint32_t kdst = sbU + (bufsel ? K1B : K0B);
        const uint32_t vdst = sbU + (bufsel ? V1B : V0B);
        #pragma unroll
        for (int i = 0; i < 4; i++) {           // K: 64 t-rows x 256B
            int idx = tid + i * 256;
            int row = idx >> 4, c = idx & 15;
            cp16(kdst + row * (LDK*4) + c * 16,
                 Kg + (size_t)(k0 + row) * HD + c * 4);
        }
        #pragma unroll
        for (int i = 0; i < 4; i++) {           // V^T: 64 hd-rows x 256B
            int idx = tid + i * 256;
            int row = idx >> 4, c = idx & 15;
            cp16(vdst + row * (LDV*4) + c * 16,
                 Vg + (size_t)row * TT + k0 + c * 4);
        }
        if (tid < 16) {
            const int* tb = (k0 < T_) ? (t_self + b * T_ + k0)
                                      : (t_cross + b * T_ + k0 - T_);
            cp16(sbU + (bufsel ? T1B : T0B) + tid * 16, tb + tid * 4);
        }
        CP_COMMIT();
    };
    issue(0, 0);

    const int wr = q0 + wid * 16;

    // Q fragments resident (natural hd indices; K side carries the interleave)
    uint32_t aQ[8][4];
    {
        const float* qp0 = Qg + (size_t)(wr + g) * HD;
        const float* qp1 = Qg + (size_t)(wr + g + 8) * HD;
        #pragma unroll
        for (int s = 0; s < 8; s++) {
            aQ[s][0] = __float_as_uint(qp0[s*8 + th]);
            aQ[s][1] = __float_as_uint(qp1[s*8 + th]);
            aQ[s][2] = __float_as_uint(qp0[s*8 + th + 4]);
            aQ[s][3] = __float_as_uint(qp1[s*8 + th + 4]);
        }
    }
    int tq[2];
    #pragma unroll
    for (int rr = 0; rr < 2; rr++) {
        int qg = wr + g + rr*8;
        tq[rr] = (qg < T_) ? t_self[b*T_ + qg] : t_cross[b*T_ + qg - T_];
    }

    float oacc[8][4];
    #pragma unroll
    for (int n = 0; n < 8; n++)
        #pragma unroll
        for (int j = 0; j < 4; j++) oacc[n][j] = 0.f;
    float l0 = 0.f, l1 = 0.f;

    float* Pw = (float*)(smc + PB) + wid * 16 * LDP;
    const float E = 0.125f * 1.44269504f;

    #pragma unroll 1
    for (int kt = 0; kt < NKT; kt++) {
        const int buf = kt & 1;
        if (kt < NKT - 1) { issue(kt + 1, buf ^ 1); CP_WAIT(1); }
        else              { CP_WAIT(0); }
        __syncthreads();

        const float* Ks  = (const float*)(smc + (buf ? K1B : K0B));
        const float* Vs  = (const float*)(smc + (buf ? V1B : V0B));
        const int*   tks = (const int*)(smc + (buf ? T1B : T0B));

        // ---- S = Q K^T, mask/exp, store P (tf32) ----
        #pragma unroll
        for (int nb = 0; nb < 8; nb++) {
            float sa[4] = {0.f, 0.f, 0.f, 0.f};
            const float* krow = &Ks[(nb*8 + g) * LDK];
            #pragma unroll
            for (int s = 0; s < 8; s++) {
                uint2 kb = *(const uint2*)&krow[s*8 + 2*th];   // LDS.64, conflict-free
                mma16n8k8(sa, aQ[s], kb.x, kb.y);
            }
            const int c0 = nb*8 + 2*th;
            const int tk0 = tks[c0], tk1 = tks[c0 + 1];

            float p00 = (tq[0] >= tk0) ? fexp2(sa[0] * E) : 0.f;
            float p01 = (tq[0] >= tk1) ? fexp2(sa[1] * E) : 0.f;
            float p10 = (tq[1] >= tk0) ? fexp2(sa[2] * E) : 0.f;
            float p11 = (tq[1] >= tk1) ? fexp2(sa[3] * E) : 0.f;
            l0 += p00 + p01;  l1 += p10 + p11;
            *(uint2*)&Pw[g * LDP + c0]       = make_uint2(f2tf32(p00), f2tf32(p01));
            *(uint2*)&Pw[(g + 8) * LDP + c0] = make_uint2(f2tf32(p10), f2tf32(p11));
        }
        __syncwarp();   // P is per-warp private

        // ---- O += P V (tf32 m16n8k8; V^T rows = hd, t interleaved) ----
        #pragma unroll
        for (int s2 = 0; s2 < 8; s2++) {
            uint32_t aP[4];
            aP[0] = __float_as_uint(Pw[g * LDP + s2*8 + th]);
            aP[1] = __float_as_uint(Pw[(g + 8) * LDP + s2*8 + th]);
            aP[2] = __float_as_uint(Pw[g * LDP + s2*8 + th + 4]);
            aP[3] = __float_as_uint(Pw[(g + 8) * LDP + s2*8 + th + 4]);
            #pragma unroll
            for (int nb2 = 0; nb2 < 8; nb2++) {
                const float* vrow = &Vs[(nb2*8 + g) * LDV];
                uint2 vb = *(const uint2*)&vrow[s2*8 + 2*th];  // LDS.64, conflict-free
                mma16n8k8(oacc[nb2], aP, vb.x, vb.y);
            }
        }
        __syncthreads();   // all reads of buf done before refill
    }

    l0 += __shfl_xor_sync(0xffffffffu, l0, 1);
    l0 += __shfl_xor_sync(0xffffffffu, l0, 2);
    l1 += __shfl_xor_sync(0xffffffffu, l1, 1);
    l1 += __shfl_xor_sync(0xffffffffu, l1, 2);
    float inv[2] = {1.f / l0, 1.f / l1};

    #pragma unroll
    for (int rr = 0; rr < 2; rr++) {
        int row = wr + g + rr*8;
        float* d = g_Y + ((size_t)(b * TT + row)) * D_ + h * HD;
        #pragma unroll
        for (int nb2 = 0; nb2 < 8; nb2++) {
            int c = nb2*8 + 2*th;
            *(uint2*)&d[c] = make_uint2(f2tf32(oacc[nb2][rr*2+0] * inv[rr]),
                                        f2tf32(oacc[nb2][rr*2+1] * inv[rr]));
        }
    }
}

// ============================================================================
// Proj GEMM, tf32 mma.sync, cp.async double-buffered (unchanged)
// ============================================================================
__global__ __launch_bounds__(256, 2) void proj_mma(
    const float* __restrict__ bias, float* __restrict__ out)
{
    extern __shared__ float smf[];
    const uint32_t sbU = smem_u32(smf);

    const int tid  = threadIdx.x;
    const int wid  = tid >> 5, lane = tid & 31;
    const int g = lane >> 2, th = lane & 3;
    const int wm = wid & 3, wn = wid >> 2;
    const int m0 = blockIdx.y * 128, n0 = blockIdx.x * 128;

    auto stage = [&](int k0, int buf) {
        const uint32_t adst = sbU + (buf ? (uint32_t)(SLABF*4) : 0u);
        const uint32_t bdst = adst + ABYTES;
        #pragma unroll
        for (int i = 0; i < 4; i++) {
            int cid = tid + i * 256;
            int r = cid >> 3, kc = cid & 7;
            cp16(adst + (r*LDA + kc*4)*4, g_Y + (size_t)(m0 + r)*512 + k0 + kc*4);
        }
        #pragma unroll
        for (int i = 0; i < 4; i++) {
            int cid = tid + i * 256;
            int kr = cid >> 5, nc = cid & 31;
            cp16(bdst + (kr*LDB + nc*4)*4, g_rWp + (size_t)(k0 + kr)*512 + n0 + nc*4);
        }
        CP_COMMIT();
    };

    float acc[2][8][4];
    #pragma unroll
    for (int mt = 0; mt < 2; mt++)
        #pragma unroll
        for (int nt = 0; nt < 8; nt++)
            #pragma unroll
            for (int j = 0; j < 4; j++) acc[mt][nt][j] = 0.f;

    stage(0, 0);
    #pragma unroll 1
    for (int it = 0; it < 16; it++) {
        const int buf = it & 1;
        if (it < 15) { stage((it + 1) * 32, buf ^ 1); CP_WAIT(1); }
        else         { CP_WAIT(0); }
        __syncthreads();

        const float* As = smf + (buf ? SLABF : 0);
        const float* Bs = As + 128*LDA;

        #pragma unroll
        for (int s = 0; s < 4; s++) {
            uint32_t aF[2][4];
            #pragma unroll
            for (int mt = 0; mt < 2; mt++) {
                int rb = wm * 32 + mt * 16 + g;
                aF[mt][0] = __float_as_uint(As[rb * LDA + s*8 + th]);
                aF[mt][1] = __float_as_uint(As[(rb + 8) * LDA + s*8 + th]);
                aF[mt][2] = __float_as_uint(As[rb * LDA + s*8 + th + 4]);
                aF[mt][3] = __float_as_uint(As[(rb + 8) * LDA + s*8 + th + 4]);
            }
            #pragma unroll
            for (int nt = 0; nt < 8; nt++) {
                int nc = wn * 64 + nt * 8 + g;
                uint32_t b0 = __float_as_uint(Bs[(s*8 + th) * LDB + nc]);
                uint32_t b1 = __float_as_uint(Bs[(s*8 + th + 4) * LDB + nc]);
                mma16n8k8(acc[0][nt], aF[0], b0, b1);
                mma16n8k8(acc[1][nt], aF[1], b0, b1);
            }
        }
        __syncthreads();
    }

    #pragma unroll
    for (int mt = 0; mt < 2; mt++) {
        #pragma unroll
        for (int r2 = 0; r2 < 2; r2++) {
            int row = m0 + wm * 32 + mt * 16 + g + r2 * 8;
            int bb = row >> 11;
            int tt = row & 2047;
            size_t base = (tt < T_)
                ? ((size_t)(bb * T_ + tt) * D_)
                : ((size_t)B_ * T_ * D_ + (size_t)(bb * T_ + (tt - T_)) * D_);
            #pragma unroll
            for (int nt = 0; nt < 8; nt++) {
                int col = n0 + wn * 64 + nt * 8 + 2 * th;
                float2 v = make_float2(acc[mt][nt][r2*2+0] + bias[col],
                                       acc[mt][nt][r2*2+1] + bias[col+1]);
                *(float2*)&out[base + col] = v;
            }
        }
    }
}

// ---------------------------------------------------------------------------
extern "C" void kernel_launch(void* const* d_in, const int* in_sizes, int n_in,
                              void* d_out, int out_size)
{
    const float* self_seq  = (const float*)d_in[0];
    const float* cross_seq = (const float*)d_in[1];
    const int*   t_self    = (const int*)d_in[2];
    const int*   t_cross   = (const int*)d_in[3];
    const float* W_self    = (const float*)d_in[4];
    const float* b_self    = (const float*)d_in[5];
    const float* W_cross   = (const float*)d_in[6];
    const float* b_cross   = (const float*)d_in[7];
    const float* W_proj    = (const float*)d_in[8];
    const float* b_proj    = (const float*)d_in[9];
    float* out = (float*)d_out;

    cudaFuncSetAttribute(attn_mma,
                         cudaFuncAttributeMaxDynamicSharedMemorySize, ATTN_SMEM);
    cudaFuncSetAttribute(qkv_mma,
                         cudaFuncAttributeMaxDynamicSharedMemorySize, GEMM_SMEM);
    cudaFuncSetAttribute(proj_mma,
                         cudaFuncAttributeMaxDynamicSharedMemorySize, GEMM_SMEM);

    round_all<<<(N4_TOT + 255)/256, 256>>>(self_seq, cross_seq,
                                           W_self, W_cross, W_proj);

    qkv_mma<<<dim3(12, 32, 2), 256, GEMM_SMEM>>>(b_self, b_cross);

    attn_mma<<<dim3(16, 32), 256, ATTN_SMEM>>>(t_self, t_cross);

    proj_mma<<<dim3(4, 64), 256, GEMM_SMEM>>>(b_proj, out);
}